// round 3
// baseline (speedup 1.0000x reference)
#include <cuda_runtime.h>

#define NN 1024
#define HH 128

// Device-global scratch (no allocation allowed)
__device__ float g_part[8 * NN * HH];     // per-jblock partial aggregates
__device__ float g_wt_ih[HH * 3 * HH];    // w_ih^T : [128][384]
__device__ float g_wt_hh[HH * 3 * HH];    // w_hh^T : [128][384]
__device__ float g_sr [NN * HH];
__device__ float g_sz [NN * HH];
__device__ float g_sni[NN * HH];
__device__ float g_snh[NN * HH];

// ---------------------------------------------------------------------------
// Transpose [384][128] -> [128][384] via padded smem tile (coalesced both ways)
// grid (12, 4), block 256 (32 x 8)
// ---------------------------------------------------------------------------
__global__ __launch_bounds__(256) void transpose_kernel(
    const float* __restrict__ W, float* __restrict__ WT)
{
    __shared__ float tile[32][33];
    const int r0 = blockIdx.x * 32;      // row block in W (384 dim)
    const int c0 = blockIdx.y * 32;      // col block in W (128 dim)
    const int tx = threadIdx.x & 31;
    const int ty = threadIdx.x >> 5;     // 0..7

    #pragma unroll
    for (int rr = ty; rr < 32; rr += 8)
        tile[rr][tx] = W[(r0 + rr) * 128 + c0 + tx];
    __syncthreads();
    #pragma unroll
    for (int rr = ty; rr < 32; rr += 8)
        WT[(c0 + rr) * 384 + r0 + tx] = tile[tx][rr];
}

// ---------------------------------------------------------------------------
// Kernel 1: partial aggregation over a j-block with smem-staged nf tile.
// grid (128 iblocks, 8 jblocks), block 256 (8 warps).
// Warp w owns row i = ib*8+w. nf[jb*128 .. +128) staged once in smem and
// reused by all 8 warps -> nf LTS traffic / 8. Warp-local ballot-scan
// compaction of adjacency; branch-free gated T loads (__ldcs, streaming).
// Output: g_part[jb][i][h] (no atomics; gru_mm sums the 8 partials).
// ---------------------------------------------------------------------------
__global__ __launch_bounds__(256) void agg_kernel(
    const float* __restrict__ nf,
    const int*   __restrict__ adj,
    const float* __restrict__ T)
{
    const int ib   = blockIdx.x;
    const int jb   = blockIdx.y;
    const int tid  = threadIdx.x;
    const int lane = tid & 31;
    const int w    = tid >> 5;
    const int i    = ib * 8 + w;

    __shared__ float4 snf[128][32];            // 64 KB nf tile
    __shared__ unsigned short slist[8][128];   // per-warp active-j list

    // Stage nf tile (coalesced)
    const float4* nf4 = (const float4*)nf;
    #pragma unroll
    for (int e = tid; e < 128 * 32; e += 256) {
        int r = e >> 5, c = e & 31;
        snf[r][c] = nf4[(jb * 128 + r) * 32 + c];
    }

    // Warp-local compaction: one int4 of adjacency per lane (128 j per warp)
    const int4 a = ((const int4*)adj)[(size_t)i * 256 + jb * 32 + lane];
    const int f0 = (a.x != 0), f1 = (a.y != 0), f2 = (a.z != 0), f3 = (a.w != 0);
    const int cnt = f0 + f1 + f2 + f3;
    int pre = cnt;
    #pragma unroll
    for (int d = 1; d < 32; d <<= 1) {
        int v = __shfl_up_sync(0xffffffffu, pre, d);
        if (lane >= d) pre += v;
    }
    const int total = __shfl_sync(0xffffffffu, pre, 31);
    pre -= cnt;                                 // exclusive prefix
    {
        unsigned short* lst = slist[w];
        int p = pre, j0 = lane * 4;
        if (f0) lst[p++] = (unsigned short)(j0);
        if (f1) lst[p++] = (unsigned short)(j0 + 1);
        if (f2) lst[p++] = (unsigned short)(j0 + 2);
        if (f3) lst[p++] = (unsigned short)(j0 + 3);
    }
    __syncthreads();

    const float4* T4 = (const float4*)T;
    const size_t rowbase = (size_t)i * NN + jb * 128;
    const unsigned short* lst = slist[w];

    float4 a0 = make_float4(0.f,0.f,0.f,0.f);
    float4 a1 = make_float4(0.f,0.f,0.f,0.f);
    float4 a2 = make_float4(0.f,0.f,0.f,0.f);
    float4 a3 = make_float4(0.f,0.f,0.f,0.f);

    int e = 0;
    for (; e + 3 < total; e += 4) {
        const int j0 = lst[e], j1 = lst[e+1], j2 = lst[e+2], j3 = lst[e+3];
        float4 t0 = __ldcs(&T4[(rowbase + j0) * 32 + lane]);
        float4 t1 = __ldcs(&T4[(rowbase + j1) * 32 + lane]);
        float4 t2 = __ldcs(&T4[(rowbase + j2) * 32 + lane]);
        float4 t3 = __ldcs(&T4[(rowbase + j3) * 32 + lane]);
        float4 f0v = snf[j0][lane];
        float4 f1v = snf[j1][lane];
        float4 f2v = snf[j2][lane];
        float4 f3v = snf[j3][lane];
        a0.x += f0v.x*t0.x; a0.y += f0v.y*t0.y; a0.z += f0v.z*t0.z; a0.w += f0v.w*t0.w;
        a1.x += f1v.x*t1.x; a1.y += f1v.y*t1.y; a1.z += f1v.z*t1.z; a1.w += f1v.w*t1.w;
        a2.x += f2v.x*t2.x; a2.y += f2v.y*t2.y; a2.z += f2v.z*t2.z; a2.w += f2v.w*t2.w;
        a3.x += f3v.x*t3.x; a3.y += f3v.y*t3.y; a3.z += f3v.z*t3.z; a3.w += f3v.w*t3.w;
    }
    for (; e < total; e++) {
        const int j = lst[e];
        float4 t = __ldcs(&T4[(rowbase + j) * 32 + lane]);
        float4 f = snf[j][lane];
        a0.x += f.x*t.x; a0.y += f.y*t.y; a0.z += f.z*t.z; a0.w += f.w*t.w;
    }

    a0.x += a1.x + a2.x + a3.x;
    a0.y += a1.y + a2.y + a3.y;
    a0.z += a1.z + a2.z + a3.z;
    a0.w += a1.w + a2.w + a3.w;

    ((float4*)g_part)[((size_t)jb * NN + i) * 32 + lane] = a0;
}

// ---------------------------------------------------------------------------
// Kernel 2a: per-gate GEMM with transposed (coalesced) weights.
// grid (128, 3), block 256. ty = tid>>5 owns row i = ib*8+ty;
// lane owns 4 output columns (lane*4) of gate g.
// Per k: one float4 of WT_ih, one of WT_hh (coalesced, L1-broadcast across
// the 8 ty-warps); inputs broadcast from smem.
// ---------------------------------------------------------------------------
__global__ __launch_bounds__(256) void gru_mm_kernel(
    const float* __restrict__ nf,
    const float* __restrict__ bih,
    const float* __restrict__ bhh)
{
    const int ib   = blockIdx.x;
    const int g    = blockIdx.y;
    const int tid  = threadIdx.x;
    const int lane = tid & 31;
    const int ty   = tid >> 5;           // i within tile
    const int i    = ib * 8 + ty;

    __shared__ float sA[8][128];
    __shared__ float sH[8][128];

    // Load inputs; sum the 8 aggregation partials here.
    #pragma unroll
    for (int e = tid; e < 8 * 32; e += 256) {
        const int il = e >> 5, c = e & 31;
        const size_t row = (size_t)(ib * 8 + il);
        float4 s = ((const float4*)g_part)[row * 32 + c];
        #pragma unroll
        for (int p = 1; p < 8; p++) {
            float4 v = ((const float4*)g_part)[((size_t)p * NN + row) * 32 + c];
            s.x += v.x; s.y += v.y; s.z += v.z; s.w += v.w;
        }
        ((float4*)sA)[e] = s;
        ((float4*)sH)[e] = ((const float4*)nf)[row * 32 + c];
    }
    __syncthreads();

    const float4* wt_i = (const float4*)g_wt_ih;   // [128][96] float4
    const float4* wt_h = (const float4*)g_wt_hh;
    const int coff = g * 32 + lane;                // float4 column within 96

    float4 ai = make_float4(0.f,0.f,0.f,0.f);
    float4 ah = make_float4(0.f,0.f,0.f,0.f);

    #pragma unroll 4
    for (int k = 0; k < 128; k++) {
        float4 wv = wt_i[k * 96 + coff];
        float4 vv = wt_h[k * 96 + coff];
        const float av = sA[ty][k];
        const float xv = sH[ty][k];
        ai.x += av * wv.x; ai.y += av * wv.y; ai.z += av * wv.z; ai.w += av * wv.w;
        ah.x += xv * vv.x; ah.y += xv * vv.y; ah.z += xv * vv.z; ah.w += xv * vv.w;
    }

    const float4 bi = ((const float4*)bih)[g * 32 + lane];
    const float4 bh = ((const float4*)bhh)[g * 32 + lane];
    const size_t oidx = (size_t)i * 32 + lane;

    if (g == 0) {
        float4 o = make_float4(ai.x+ah.x+bi.x+bh.x, ai.y+ah.y+bi.y+bh.y,
                               ai.z+ah.z+bi.z+bh.z, ai.w+ah.w+bi.w+bh.w);
        ((float4*)g_sr)[oidx] = o;
    } else if (g == 1) {
        float4 o = make_float4(ai.x+ah.x+bi.x+bh.x, ai.y+ah.y+bi.y+bh.y,
                               ai.z+ah.z+bi.z+bh.z, ai.w+ah.w+bi.w+bh.w);
        ((float4*)g_sz)[oidx] = o;
    } else {
        float4 o1 = make_float4(ai.x+bi.x, ai.y+bi.y, ai.z+bi.z, ai.w+bi.w);
        float4 o2 = make_float4(ah.x+bh.x, ah.y+bh.y, ah.z+bh.z, ah.w+bh.w);
        ((float4*)g_sni)[oidx] = o1;
        ((float4*)g_snh)[oidx] = o2;
    }
}

// ---------------------------------------------------------------------------
// Kernel 2b: elementwise gate fusion.
// ---------------------------------------------------------------------------
__global__ __launch_bounds__(256) void gru_ep_kernel(
    const float* __restrict__ nf,
    float*       __restrict__ out)
{
    const int idx = blockIdx.x * 256 + threadIdx.x;
    const float r = 1.f / (1.f + __expf(-g_sr[idx]));
    const float z = 1.f / (1.f + __expf(-g_sz[idx]));
    const float n = tanhf(g_sni[idx] + r * g_snh[idx]);
    out[idx] = (1.f - z) * n + z * nf[idx];
}

extern "C" void kernel_launch(void* const* d_in, const int* in_sizes, int n_in,
                              void* d_out, int out_size)
{
    const float* nf  = (const float*)d_in[0];
    const int*   adj = (const int*)  d_in[1];
    const float* T   = (const float*)d_in[2];
    const float* wih = (const float*)d_in[3];
    const float* whh = (const float*)d_in[4];
    const float* bih = (const float*)d_in[5];
    const float* bhh = (const float*)d_in[6];
    float* out = (float*)d_out;

    float *wt_ih_p, *wt_hh_p;
    cudaGetSymbolAddress((void**)&wt_ih_p, g_wt_ih);
    cudaGetSymbolAddress((void**)&wt_hh_p, g_wt_hh);

    agg_kernel<<<dim3(NN / 8, 8), 256>>>(nf, adj, T);
    transpose_kernel<<<dim3(12, 4), 256>>>(wih, wt_ih_p);
    transpose_kernel<<<dim3(12, 4), 256>>>(whh, wt_hh_p);
    gru_mm_kernel<<<dim3(NN / 8, 3), 256>>>(nf, bih, bhh);
    gru_ep_kernel<<<(NN * HH) / 256, 256>>>(nf, out);
}

// round 4
// speedup vs baseline: 1.3599x; 1.3599x over previous
#include <cuda_runtime.h>

#define NN 1024
#define HH 128

// Device-global scratch (no allocation allowed)
__device__ float g_part[8 * NN * HH];     // per-jblock partial aggregates
__device__ float g_agg [NN * HH];         // summed aggregate
__device__ float g_wt_ih[HH * 3 * HH];    // w_ih^T : [128][384]
__device__ float g_wt_hh[HH * 3 * HH];    // w_hh^T : [128][384]
__device__ float g_gi[NN * 3 * HH];       // gi = agg @ w_ih^T   [1024][384]
__device__ float g_gh[NN * 3 * HH];       // gh = nf  @ w_hh^T   [1024][384]

// ---------------------------------------------------------------------------
// Transpose [384][128] -> [128][384]. grid (12, 4, 2): z picks ih/hh.
// ---------------------------------------------------------------------------
__global__ __launch_bounds__(256) void transpose_kernel(
    const float* __restrict__ Wih, const float* __restrict__ Whh)
{
    __shared__ float tile[32][33];
    const float* W  = blockIdx.z ? Whh : Wih;
    float*       WT = blockIdx.z ? g_wt_hh : g_wt_ih;
    const int r0 = blockIdx.x * 32;      // row block in W (384 dim)
    const int c0 = blockIdx.y * 32;      // col block in W (128 dim)
    const int tx = threadIdx.x & 31;
    const int ty = threadIdx.x >> 5;

    #pragma unroll
    for (int rr = ty; rr < 32; rr += 8)
        tile[rr][tx] = W[(r0 + rr) * 128 + c0 + tx];
    __syncthreads();
    #pragma unroll
    for (int rr = ty; rr < 32; rr += 8)
        WT[(c0 + rr) * 384 + r0 + tx] = tile[tx][rr];
}

// ---------------------------------------------------------------------------
// Kernel 1: partial aggregation (unchanged from round 3 — measured ~40us).
// ---------------------------------------------------------------------------
__global__ __launch_bounds__(256) void agg_kernel(
    const float* __restrict__ nf,
    const int*   __restrict__ adj,
    const float* __restrict__ T)
{
    const int ib   = blockIdx.x;
    const int jb   = blockIdx.y;
    const int tid  = threadIdx.x;
    const int lane = tid & 31;
    const int w    = tid >> 5;
    const int i    = ib * 8 + w;

    __shared__ float4 snf[128][32];
    __shared__ unsigned short slist[8][128];

    const float4* nf4 = (const float4*)nf;
    #pragma unroll
    for (int e = tid; e < 128 * 32; e += 256) {
        int r = e >> 5, c = e & 31;
        snf[r][c] = nf4[(jb * 128 + r) * 32 + c];
    }

    const int4 a = ((const int4*)adj)[(size_t)i * 256 + jb * 32 + lane];
    const int f0 = (a.x != 0), f1 = (a.y != 0), f2 = (a.z != 0), f3 = (a.w != 0);
    const int cnt = f0 + f1 + f2 + f3;
    int pre = cnt;
    #pragma unroll
    for (int d = 1; d < 32; d <<= 1) {
        int v = __shfl_up_sync(0xffffffffu, pre, d);
        if (lane >= d) pre += v;
    }
    const int total = __shfl_sync(0xffffffffu, pre, 31);
    pre -= cnt;
    {
        unsigned short* lst = slist[w];
        int p = pre, j0 = lane * 4;
        if (f0) lst[p++] = (unsigned short)(j0);
        if (f1) lst[p++] = (unsigned short)(j0 + 1);
        if (f2) lst[p++] = (unsigned short)(j0 + 2);
        if (f3) lst[p++] = (unsigned short)(j0 + 3);
    }
    __syncthreads();

    const float4* T4 = (const float4*)T;
    const size_t rowbase = (size_t)i * NN + jb * 128;
    const unsigned short* lst = slist[w];

    float4 a0 = make_float4(0.f,0.f,0.f,0.f);
    float4 a1 = make_float4(0.f,0.f,0.f,0.f);
    float4 a2 = make_float4(0.f,0.f,0.f,0.f);
    float4 a3 = make_float4(0.f,0.f,0.f,0.f);

    int e = 0;
    for (; e + 3 < total; e += 4) {
        const int j0 = lst[e], j1 = lst[e+1], j2 = lst[e+2], j3 = lst[e+3];
        float4 t0 = __ldcs(&T4[(rowbase + j0) * 32 + lane]);
        float4 t1 = __ldcs(&T4[(rowbase + j1) * 32 + lane]);
        float4 t2 = __ldcs(&T4[(rowbase + j2) * 32 + lane]);
        float4 t3 = __ldcs(&T4[(rowbase + j3) * 32 + lane]);
        float4 f0v = snf[j0][lane];
        float4 f1v = snf[j1][lane];
        float4 f2v = snf[j2][lane];
        float4 f3v = snf[j3][lane];
        a0.x += f0v.x*t0.x; a0.y += f0v.y*t0.y; a0.z += f0v.z*t0.z; a0.w += f0v.w*t0.w;
        a1.x += f1v.x*t1.x; a1.y += f1v.y*t1.y; a1.z += f1v.z*t1.z; a1.w += f1v.w*t1.w;
        a2.x += f2v.x*t2.x; a2.y += f2v.y*t2.y; a2.z += f2v.z*t2.z; a2.w += f2v.w*t2.w;
        a3.x += f3v.x*t3.x; a3.y += f3v.y*t3.y; a3.z += f3v.z*t3.z; a3.w += f3v.w*t3.w;
    }
    for (; e < total; e++) {
        const int j = lst[e];
        float4 t = __ldcs(&T4[(rowbase + j) * 32 + lane]);
        float4 f = snf[j][lane];
        a0.x += f.x*t.x; a0.y += f.y*t.y; a0.z += f.z*t.z; a0.w += f.w*t.w;
    }

    a0.x += a1.x + a2.x + a3.x;
    a0.y += a1.y + a2.y + a3.y;
    a0.z += a1.z + a2.z + a3.z;
    a0.w += a1.w + a2.w + a3.w;

    ((float4*)g_part)[((size_t)jb * NN + i) * 32 + lane] = a0;
}

// ---------------------------------------------------------------------------
// Kernel 1b: sum the 8 j-block partials into g_agg. 32768 float4s.
// ---------------------------------------------------------------------------
__global__ __launch_bounds__(256) void sum_kernel()
{
    const int e = blockIdx.x * 256 + threadIdx.x;   // float4 index
    float4 s = ((const float4*)g_part)[e];
    #pragma unroll
    for (int p = 1; p < 8; p++) {
        float4 v = ((const float4*)g_part)[p * (NN * HH / 4) + e];
        s.x += v.x; s.y += v.y; s.z += v.z; s.w += v.w;
    }
    ((float4*)g_agg)[e] = s;
}

// ---------------------------------------------------------------------------
// Kernel 2: tiled GEMM  C[1024 x 384] = A[1024 x 128] @ WT[128 x 384].
// grid (16 mtiles, 6 ntiles, 2): z=0 -> A=g_agg, C=g_gi, W=g_wt_ih
//                                z=1 -> A=nf,    C=g_gh, W=g_wt_hh
// block 256 = 16x16 threads; each thread computes 4x4 outputs.
// K=128 processed in two 64-passes (smem 2 x 16KB, static <48KB).
// Inner 4-k chunk: 8 LDS.128 vs 64 FFMA.
// ---------------------------------------------------------------------------
__global__ __launch_bounds__(256) void gemm_kernel(const float* __restrict__ nf)
{
    const int mt  = blockIdx.x;            // m tile (64 rows)
    const int nt  = blockIdx.y;            // n tile (64 cols)
    const int zz  = blockIdx.z;
    const int tid = threadIdx.x;
    const int tx  = tid & 15;              // n thread
    const int ty  = tid >> 4;              // m thread

    const float4* A4  = (const float4*)(zz ? nf : g_agg);
    const float4* WT4 = (const float4*)(zz ? g_wt_hh : g_wt_ih);
    float4*       C4  = (float4*)(zz ? g_gh : g_gi);

    __shared__ float4 sA[64][16];          // [m][k4] 16 KB
    __shared__ float4 sB[64][16];          // [k][n4] 16 KB

    const int mbase  = mt * 64;
    const int nbase4 = nt * 16;            // float4 col base (of 96)

    float4 c0 = make_float4(0,0,0,0), c1 = make_float4(0,0,0,0);
    float4 c2 = make_float4(0,0,0,0), c3 = make_float4(0,0,0,0);
    float4 c4 = make_float4(0,0,0,0), c5 = make_float4(0,0,0,0);
    float4 c6 = make_float4(0,0,0,0), c7 = make_float4(0,0,0,0);
    float4 c8 = make_float4(0,0,0,0), c9 = make_float4(0,0,0,0);
    float4 ca = make_float4(0,0,0,0), cb = make_float4(0,0,0,0);
    float4 cc = make_float4(0,0,0,0), cd = make_float4(0,0,0,0);
    float4 ce = make_float4(0,0,0,0), cf = make_float4(0,0,0,0);

    #pragma unroll
    for (int kb = 0; kb < 2; kb++) {
        // Stage A: 64 rows x 16 float4 (k-slice). Coalesced, conflict-free.
        #pragma unroll
        for (int e = tid; e < 64 * 16; e += 256) {
            const int m = e >> 4, kq = e & 15;
            sA[m][kq] = A4[(size_t)(mbase + m) * 32 + kb * 16 + kq];
        }
        // Stage B: 64 k-rows x 16 float4 (n-slice). Coalesced, conflict-free.
        #pragma unroll
        for (int e = tid; e < 64 * 16; e += 256) {
            const int k = e >> 4, nq = e & 15;
            sB[k][nq] = WT4[(size_t)(kb * 64 + k) * 96 + nbase4 + nq];
        }
        __syncthreads();

        #pragma unroll
        for (int k = 0; k < 64; k += 4) {
            const float4 b0 = sB[k + 0][tx];
            const float4 b1 = sB[k + 1][tx];
            const float4 b2 = sB[k + 2][tx];
            const float4 b3 = sB[k + 3][tx];
            const float4 a0 = sA[ty * 4 + 0][k >> 2];
            const float4 a1 = sA[ty * 4 + 1][k >> 2];
            const float4 a2 = sA[ty * 4 + 2][k >> 2];
            const float4 a3 = sA[ty * 4 + 3][k >> 2];

            c0.x += a0.x*b0.x; c0.y += a0.x*b0.y; c0.z += a0.x*b0.z; c0.w += a0.x*b0.w;
            c1.x += a0.y*b1.x; c1.y += a0.y*b1.y; c1.z += a0.y*b1.z; c1.w += a0.y*b1.w;
            c2.x += a0.z*b2.x; c2.y += a0.z*b2.y; c2.z += a0.z*b2.z; c2.w += a0.z*b2.w;
            c3.x += a0.w*b3.x; c3.y += a0.w*b3.y; c3.z += a0.w*b3.z; c3.w += a0.w*b3.w;

            c4.x += a1.x*b0.x; c4.y += a1.x*b0.y; c4.z += a1.x*b0.z; c4.w += a1.x*b0.w;
            c5.x += a1.y*b1.x; c5.y += a1.y*b1.y; c5.z += a1.y*b1.z; c5.w += a1.y*b1.w;
            c6.x += a1.z*b2.x; c6.y += a1.z*b2.y; c6.z += a1.z*b2.z; c6.w += a1.z*b2.w;
            c7.x += a1.w*b3.x; c7.y += a1.w*b3.y; c7.z += a1.w*b3.z; c7.w += a1.w*b3.w;

            c8.x += a2.x*b0.x; c8.y += a2.x*b0.y; c8.z += a2.x*b0.z; c8.w += a2.x*b0.w;
            c9.x += a2.y*b1.x; c9.y += a2.y*b1.y; c9.z += a2.y*b1.z; c9.w += a2.y*b1.w;
            ca.x += a2.z*b2.x; ca.y += a2.z*b2.y; ca.z += a2.z*b2.z; ca.w += a2.z*b2.w;
            cb.x += a2.w*b3.x; cb.y += a2.w*b3.y; cb.z += a2.w*b3.z; cb.w += a2.w*b3.w;

            cc.x += a3.x*b0.x; cc.y += a3.x*b0.y; cc.z += a3.x*b0.z; cc.w += a3.x*b0.w;
            cd.x += a3.y*b1.x; cd.y += a3.y*b1.y; cd.z += a3.y*b1.z; cd.w += a3.y*b1.w;
            ce.x += a3.z*b2.x; ce.y += a3.z*b2.y; ce.z += a3.z*b2.z; ce.w += a3.z*b2.w;
            cf.x += a3.w*b3.x; cf.y += a3.w*b3.y; cf.z += a3.w*b3.z; cf.w += a3.w*b3.w;
        }
        __syncthreads();
    }

    // Reduce the 4 k-phase accumulators per output row and store.
    const int m0 = mbase + ty * 4;
    {
        float4 o;
        o.x = c0.x+c1.x+c2.x+c3.x; o.y = c0.y+c1.y+c2.y+c3.y;
        o.z = c0.z+c1.z+c2.z+c3.z; o.w = c0.w+c1.w+c2.w+c3.w;
        C4[(size_t)(m0 + 0) * 96 + nbase4 + tx] = o;
        o.x = c4.x+c5.x+c6.x+c7.x; o.y = c4.y+c5.y+c6.y+c7.y;
        o.z = c4.z+c5.z+c6.z+c7.z; o.w = c4.w+c5.w+c6.w+c7.w;
        C4[(size_t)(m0 + 1) * 96 + nbase4 + tx] = o;
        o.x = c8.x+c9.x+ca.x+cb.x; o.y = c8.y+c9.y+ca.y+cb.y;
        o.z = c8.z+c9.z+ca.z+cb.z; o.w = c8.w+c9.w+ca.w+cb.w;
        C4[(size_t)(m0 + 2) * 96 + nbase4 + tx] = o;
        o.x = cc.x+cd.x+ce.x+cf.x; o.y = cc.y+cd.y+ce.y+cf.y;
        o.z = cc.z+cd.z+ce.z+cf.z; o.w = cc.w+cd.w+ce.w+cf.w;
        C4[(size_t)(m0 + 3) * 96 + nbase4 + tx] = o;
    }
}

// ---------------------------------------------------------------------------
// Kernel 3: fused GRU epilogue. One thread per (i,h).
// ---------------------------------------------------------------------------
__global__ __launch_bounds__(256) void gru_ep_kernel(
    const float* __restrict__ nf,
    const float* __restrict__ bih,
    const float* __restrict__ bhh,
    float*       __restrict__ out)
{
    const int idx = blockIdx.x * 256 + threadIdx.x;   // i*128 + h
    const int i = idx >> 7;
    const int h = idx & 127;
    const size_t base = (size_t)i * 384 + h;

    const float r = 1.f / (1.f + __expf(-(g_gi[base] + g_gh[base]
                                          + bih[h] + bhh[h])));
    const float z = 1.f / (1.f + __expf(-(g_gi[base + 128] + g_gh[base + 128]
                                          + bih[h + 128] + bhh[h + 128])));
    const float n = tanhf(g_gi[base + 256] + bih[h + 256]
                          + r * (g_gh[base + 256] + bhh[h + 256]));
    out[idx] = (1.f - z) * n + z * nf[idx];
}

extern "C" void kernel_launch(void* const* d_in, const int* in_sizes, int n_in,
                              void* d_out, int out_size)
{
    const float* nf  = (const float*)d_in[0];
    const int*   adj = (const int*)  d_in[1];
    const float* T   = (const float*)d_in[2];
    const float* wih = (const float*)d_in[3];
    const float* whh = (const float*)d_in[4];
    const float* bih = (const float*)d_in[5];
    const float* bhh = (const float*)d_in[6];
    float* out = (float*)d_out;

    transpose_kernel<<<dim3(12, 4, 2), 256>>>(wih, whh);
    agg_kernel<<<dim3(NN / 8, 8), 256>>>(nf, adj, T);
    sum_kernel<<<(NN * HH / 4) / 256, 256>>>();
    gemm_kernel<<<dim3(16, 6, 2), 256>>>(nf);
    gru_ep_kernel<<<(NN * HH) / 256, 256>>>(nf, bih, bhh, out);
}